// round 2
// baseline (speedup 1.0000x reference)
#include <cuda_runtime.h>
#include <cuda_bf16.h>

// Scratch (static __device__ arrays — no allocation)
__device__ unsigned g_spk[32 * 256 * 256];     // conv1 spike bitmask (30 bits) per (t,y,x)
__device__ unsigned g_pool[32 * 129 * 129];    // pooled bitmask per (t,py,px)
__device__ float    g_wmin;                    // min over all w2 weights
__device__ int      g_flag;                    // 1 => all outputs are provably 1

// ---------------------------------------------------------------------------
// Kernel 0: min over w2 (75000 floats) + reset flag
// ---------------------------------------------------------------------------
__global__ void k_min_w2(const float* __restrict__ w2, int n) {
    __shared__ float s[256];
    int tid = threadIdx.x;
    float m = 1e30f;
    for (int i = tid; i < n; i += 256) m = fminf(m, w2[i]);
    s[tid] = m;
    __syncthreads();
    for (int off = 128; off > 0; off >>= 1) {
        if (tid < off) s[tid] = fminf(s[tid], s[tid + off]);
        __syncthreads();
    }
    if (tid == 0) { g_wmin = s[0]; g_flag = 0; }
}

// ---------------------------------------------------------------------------
// Kernel 1: conv1 (5x5, pad 2) + fire(>15) -> packed 30-bit spike masks
// Block: 32x4 threads, each thread computes 2 output rows for one x.
// Tile: 32 wide x 8 tall outputs.
// ---------------------------------------------------------------------------
__global__ __launch_bounds__(128) void k_conv1(const float* __restrict__ in,
                                               const float* __restrict__ w1,
                                               unsigned* __restrict__ spk) {
    __shared__ float in_s[2][12][36];   // rows y0-2..y0+9, cols x0-2..x0+33
    __shared__ float w_s[1500];         // [30][2][5][5]

    const int t  = blockIdx.z;
    const int x0 = blockIdx.x * 32;
    const int y0 = blockIdx.y * 8;
    const int tid = threadIdx.y * 32 + threadIdx.x;

    for (int idx = tid; idx < 864; idx += 128) {
        int ch  = idx / 432;
        int rem = idx % 432;
        int r = rem / 36, c = rem % 36;
        int gy = y0 + r - 2, gx = x0 + c - 2;
        float v = 0.0f;
        if (gy >= 0 && gy < 256 && gx >= 0 && gx < 256)
            v = in[(((t * 2 + ch) << 8) + gy) * 256 + gx];
        in_s[ch][r][c] = v;
    }
    for (int idx = tid; idx < 1500; idx += 128) w_s[idx] = w1[idx];
    __syncthreads();

    const int tx  = threadIdx.x;
    const int ty2 = threadIdx.y * 2;

    float acc0[30], acc1[30];
#pragma unroll
    for (int o = 0; o < 30; o++) { acc0[o] = 0.0f; acc1[o] = 0.0f; }

    int k = 0;
    for (int ch = 0; ch < 2; ch++) {
        for (int i = 0; i < 5; i++) {
#pragma unroll
            for (int j = 0; j < 5; j++) {
                float v0 = in_s[ch][ty2 + i][tx + j];
                float v1 = in_s[ch][ty2 + 1 + i][tx + j];
#pragma unroll
                for (int o = 0; o < 30; o++) {
                    float w = w_s[o * 50 + k];
                    acc0[o] += v0 * w;
                    acc1[o] += v1 * w;
                }
                k++;
            }
        }
    }

    unsigned m0 = 0, m1 = 0;
#pragma unroll
    for (int o = 0; o < 30; o++) {
        if (acc0[o] > 15.0f) m0 |= (1u << o);
        if (acc1[o] > 15.0f) m1 |= (1u << o);
    }
    int y = y0 + ty2;
    spk[(t << 16) + (y << 8) + x0 + tx]       = m0;
    spk[(t << 16) + ((y + 1) << 8) + x0 + tx] = m1;
}

// ---------------------------------------------------------------------------
// Kernel 2: maxpool k=2 s=2 p=1 on spike masks (OR of 2x2 window) -> 129x129
// ---------------------------------------------------------------------------
__global__ void k_pool(const unsigned* __restrict__ spk, unsigned* __restrict__ pool) {
    const int t = blockIdx.y;
    int idx = blockIdx.x * 256 + threadIdx.x;
    if (idx >= 129 * 129) return;
    int py = idx / 129, px = idx % 129;
    int r0 = 2 * py - 1, r1 = 2 * py;
    int c0 = 2 * px - 1, c1 = 2 * px;
    const unsigned* base = spk + (t << 16);
    unsigned m = 0;
    bool r0v = (r0 >= 0), r1v = (r1 < 256);
    bool c0v = (c0 >= 0), c1v = (c1 < 256);
    if (r0v && c0v) m |= base[(r0 << 8) + c0];
    if (r0v && c1v) m |= base[(r0 << 8) + c1];
    if (r1v && c0v) m |= base[(r1 << 8) + c0];
    if (r1v && c1v) m |= base[(r1 << 8) + c1];
    pool[(t * 129 + py) * 129 + px] = m;
}

// ---------------------------------------------------------------------------
// Kernel 3: scan conv2 windows; if popcount * wmin > 11, every output channel
// provably spikes at that position => all outputs are 1.
// ---------------------------------------------------------------------------
__global__ void k_scan(const unsigned* __restrict__ pool) {
    const int t = blockIdx.y;
    int idx = blockIdx.x * 256 + threadIdx.x;
    if (idx >= 127 * 127) return;
    int y = idx / 127, x = idx % 127;
    int P = 0;
#pragma unroll
    for (int ky = 0; ky < 5; ky++) {
        int ry = y + ky - 1;
        if (ry < 0 || ry > 128) continue;
#pragma unroll
        for (int kx = 0; kx < 5; kx++) {
            int rx = x + kx - 1;
            if (rx < 0 || rx > 128) continue;
            P += __popc(pool[(t * 129 + ry) * 129 + rx]);
        }
    }
    if ((float)P * g_wmin > 11.0f) g_flag = 1;
}

// ---------------------------------------------------------------------------
// Kernel 4: write output (all ones if flag; zeros otherwise as base for fallback)
// ---------------------------------------------------------------------------
__global__ void k_final(float* __restrict__ out) {
    int tid = threadIdx.x;
    if (tid < 100) out[tid] = g_flag ? 1.0f : 0.0f;
}

// ---------------------------------------------------------------------------
// Kernel 5: exact conv2 fallback — only does work when the bound never fired.
// grid (127 rows, 32 times), 128 threads. Early-exits on g_flag.
// ---------------------------------------------------------------------------
__global__ void k_conv2_fallback(const unsigned* __restrict__ pool,
                                 const float* __restrict__ w2,
                                 float* __restrict__ out) {
    if (g_flag) return;
    const int y = blockIdx.x;   // 0..126
    const int t = blockIdx.y;   // 0..31
    for (int task = threadIdx.x; task < 127 * 100; task += 128) {
        int x = task / 100;
        int o = task % 100;
        float pot = 0.0f;
        for (int ky = 0; ky < 5; ky++) {
            int ry = y + ky - 1;
            if (ry < 0 || ry > 128) continue;
            for (int kx = 0; kx < 5; kx++) {
                int rx = x + kx - 1;
                if (rx < 0 || rx > 128) continue;
                unsigned m = pool[(t * 129 + ry) * 129 + rx];
                const float* wb = w2 + ((o * 30) * 5 + ky) * 5 + kx;
                for (int i = 0; i < 30; i++) {
                    if ((m >> i) & 1u) pot += wb[i * 25];
                }
            }
        }
        if (pot > 10.0f) out[o] = 1.0f;  // races write the same value; benign
    }
}

// ---------------------------------------------------------------------------
extern "C" void kernel_launch(void* const* d_in, const int* in_sizes, int n_in,
                              void* d_out, int out_size) {
    const float* in = (const float*)d_in[0];   // [32,2,256,256]
    const float* w1 = (const float*)d_in[1];   // [30,2,5,5]
    const float* w2 = (const float*)d_in[2];   // [100,30,5,5]
    float* out = (float*)d_out;                // [1,100]

    unsigned* spk  = nullptr;
    unsigned* pool = nullptr;
    cudaGetSymbolAddress((void**)&spk,  g_spk);
    cudaGetSymbolAddress((void**)&pool, g_pool);

    // 0: wmin(w2) + flag reset
    k_min_w2<<<1, 256>>>(w2, in_sizes[2]);

    // 1: conv1 + fire -> spike masks
    dim3 g1(8, 32, 32), b1(32, 4);
    k_conv1<<<g1, b1>>>(in, w1, spk);

    // 2: maxpool(2,2,1) -> pooled masks
    dim3 g2((129 * 129 + 255) / 256, 32);
    k_pool<<<g2, 256>>>(spk, pool);

    // 3: bound scan -> flag
    dim3 g3((127 * 127 + 255) / 256, 32);
    k_scan<<<g3, 256>>>(pool);

    // 4: write outputs
    k_final<<<1, 128>>>(out);

    // 5: exact fallback (no-op when flag set)
    dim3 g5(127, 32);
    k_conv2_fallback<<<g5, 128>>>(pool, w2, out);
}

// round 3
// speedup vs baseline: 9.1711x; 9.1711x over previous
#include <cuda_runtime.h>
#include <cuda_bf16.h>

// Scratch (static __device__ arrays — no allocation)
__device__ unsigned g_spk[32 * 256 * 256];     // conv1 spike bitmask (30 bits) per (t,y,x)
__device__ unsigned g_pool[32 * 129 * 129];    // pooled bitmask per (t,py,px)
__device__ unsigned g_w1min_bits;              // order-transformed min of w1
__device__ unsigned g_w2min_bits;              // order-transformed min of w2
__device__ int      g_flag;                    // 1 => all outputs are provably 1

// Order-preserving float<->uint transform (min over keys == min over floats)
__device__ __forceinline__ unsigned f2key(float f) {
    unsigned b = __float_as_uint(f);
    return (b & 0x80000000u) ? ~b : (b | 0x80000000u);
}
__device__ __forceinline__ float key2f(unsigned k) {
    unsigned b = (k & 0x80000000u) ? (k & 0x7FFFFFFFu) : ~k;
    return __uint_as_float(b);
}

// ---------------------------------------------------------------------------
// Kernel 0: reset state
// ---------------------------------------------------------------------------
__global__ void k_init() {
    g_w1min_bits = 0xFFFFFFFFu;
    g_w2min_bits = 0xFFFFFFFFu;
    g_flag = 0;
}

// ---------------------------------------------------------------------------
// Kernel 1: parallel min over w1 (1500) and w2 (75000)
// ---------------------------------------------------------------------------
__global__ void k_minw(const float* __restrict__ w1, int n1,
                       const float* __restrict__ w2, int n2) {
    int gid = blockIdx.x * blockDim.x + threadIdx.x;
    int nth = gridDim.x * blockDim.x;
    float m1 = 1e30f, m2 = 1e30f;
    for (int i = gid; i < n1; i += nth) m1 = fminf(m1, w1[i]);
    for (int i = gid; i < n2; i += nth) m2 = fminf(m2, w2[i]);
    // warp reduce
    for (int off = 16; off > 0; off >>= 1) {
        m1 = fminf(m1, __shfl_xor_sync(0xFFFFFFFFu, m1, off));
        m2 = fminf(m2, __shfl_xor_sync(0xFFFFFFFFu, m2, off));
    }
    if ((threadIdx.x & 31) == 0) {
        atomicMin(&g_w1min_bits, f2key(m1));
        atomicMin(&g_w2min_bits, f2key(m2));
    }
}

// ---------------------------------------------------------------------------
// Kernel 2: probe t=0. If any conv1 window's active-input count S satisfies
// S*w1min > 15.01 (all 30 ch spike) and 30*w2min > 10.01 (then all 100
// conv2 channels spike at a window containing that pooled cell), the entire
// output is provably all-ones.
// ---------------------------------------------------------------------------
__global__ __launch_bounds__(128) void k_probe(const float* __restrict__ in) {
    __shared__ float in_s[2][12][36];
    const int x0 = blockIdx.x * 32;
    const int y0 = blockIdx.y * 8;
    const int tid = threadIdx.y * 32 + threadIdx.x;

    for (int idx = tid; idx < 864; idx += 128) {
        int ch  = idx / 432;
        int rem = idx % 432;
        int r = rem / 36, c = rem % 36;
        int gy = y0 + r - 2, gx = x0 + c - 2;
        float v = 0.0f;
        if (gy >= 0 && gy < 256 && gx >= 0 && gx < 256)
            v = in[((ch << 8) + gy) * 256 + gx];   // t = 0
        in_s[ch][r][c] = v;
    }
    __syncthreads();

    const int tx  = threadIdx.x;
    const int ty2 = threadIdx.y * 2;

    float s0 = 0.0f, s1 = 0.0f;
    for (int ch = 0; ch < 2; ch++) {
#pragma unroll
        for (int i = 0; i < 5; i++) {
#pragma unroll
            for (int j = 0; j < 5; j++) {
                s0 += in_s[ch][ty2 + i][tx + j];
                s1 += in_s[ch][ty2 + 1 + i][tx + j];
            }
        }
    }
    float w1min = key2f(g_w1min_bits);
    float w2min = key2f(g_w2min_bits);
    float smax = fmaxf(s0, s1);
    if (smax * w1min > 15.01f && 30.0f * w2min > 10.01f) g_flag = 1;
}

// ---------------------------------------------------------------------------
// Kernel 3: conv1 (5x5, pad 2) + fire(>15) -> packed 30-bit spike masks
// (slow path only; early-exits when g_flag is set)
// ---------------------------------------------------------------------------
__global__ __launch_bounds__(128) void k_conv1(const float* __restrict__ in,
                                               const float* __restrict__ w1,
                                               unsigned* __restrict__ spk) {
    if (g_flag) return;
    __shared__ float in_s[2][12][36];
    __shared__ float w_s[1500];

    const int t  = blockIdx.z;
    const int x0 = blockIdx.x * 32;
    const int y0 = blockIdx.y * 8;
    const int tid = threadIdx.y * 32 + threadIdx.x;

    for (int idx = tid; idx < 864; idx += 128) {
        int ch  = idx / 432;
        int rem = idx % 432;
        int r = rem / 36, c = rem % 36;
        int gy = y0 + r - 2, gx = x0 + c - 2;
        float v = 0.0f;
        if (gy >= 0 && gy < 256 && gx >= 0 && gx < 256)
            v = in[(((t * 2 + ch) << 8) + gy) * 256 + gx];
        in_s[ch][r][c] = v;
    }
    for (int idx = tid; idx < 1500; idx += 128) w_s[idx] = w1[idx];
    __syncthreads();

    const int tx  = threadIdx.x;
    const int ty2 = threadIdx.y * 2;

    float acc0[30], acc1[30];
#pragma unroll
    for (int o = 0; o < 30; o++) { acc0[o] = 0.0f; acc1[o] = 0.0f; }

    int k = 0;
    for (int ch = 0; ch < 2; ch++) {
        for (int i = 0; i < 5; i++) {
#pragma unroll
            for (int j = 0; j < 5; j++) {
                float v0 = in_s[ch][ty2 + i][tx + j];
                float v1 = in_s[ch][ty2 + 1 + i][tx + j];
#pragma unroll
                for (int o = 0; o < 30; o++) {
                    float w = w_s[o * 50 + k];
                    acc0[o] += v0 * w;
                    acc1[o] += v1 * w;
                }
                k++;
            }
        }
    }

    unsigned m0 = 0, m1 = 0;
#pragma unroll
    for (int o = 0; o < 30; o++) {
        if (acc0[o] > 15.0f) m0 |= (1u << o);
        if (acc1[o] > 15.0f) m1 |= (1u << o);
    }
    int y = y0 + ty2;
    spk[(t << 16) + (y << 8) + x0 + tx]       = m0;
    spk[(t << 16) + ((y + 1) << 8) + x0 + tx] = m1;
}

// ---------------------------------------------------------------------------
// Kernel 4: maxpool k=2 s=2 p=1 (OR of 2x2) -> 129x129  (slow path only)
// ---------------------------------------------------------------------------
__global__ void k_pool(const unsigned* __restrict__ spk, unsigned* __restrict__ pool) {
    if (g_flag) return;
    const int t = blockIdx.y;
    int idx = blockIdx.x * 256 + threadIdx.x;
    if (idx >= 129 * 129) return;
    int py = idx / 129, px = idx % 129;
    int r0 = 2 * py - 1, r1 = 2 * py;
    int c0 = 2 * px - 1, c1 = 2 * px;
    const unsigned* base = spk + (t << 16);
    unsigned m = 0;
    bool r0v = (r0 >= 0), r1v = (r1 < 256);
    bool c0v = (c0 >= 0), c1v = (c1 < 256);
    if (r0v && c0v) m |= base[(r0 << 8) + c0];
    if (r0v && c1v) m |= base[(r0 << 8) + c1];
    if (r1v && c0v) m |= base[(r1 << 8) + c0];
    if (r1v && c1v) m |= base[(r1 << 8) + c1];
    pool[(t * 129 + py) * 129 + px] = m;
}

// ---------------------------------------------------------------------------
// Kernel 5: bound scan over conv2 windows (slow path only)
// ---------------------------------------------------------------------------
__global__ void k_scan(const unsigned* __restrict__ pool) {
    if (g_flag) return;
    const int t = blockIdx.y;
    int idx = blockIdx.x * 256 + threadIdx.x;
    if (idx >= 127 * 127) return;
    int y = idx / 127, x = idx % 127;
    int P = 0;
#pragma unroll
    for (int ky = 0; ky < 5; ky++) {
        int ry = y + ky - 1;
        if (ry < 0 || ry > 128) continue;
#pragma unroll
        for (int kx = 0; kx < 5; kx++) {
            int rx = x + kx - 1;
            if (rx < 0 || rx > 128) continue;
            P += __popc(pool[(t * 129 + ry) * 129 + rx]);
        }
    }
    float w2min = key2f(g_w2min_bits);
    if ((float)P * w2min > 11.0f) g_flag = 1;
}

// ---------------------------------------------------------------------------
// Kernel 6: write output base (ones if proven, zeros for fallback)
// ---------------------------------------------------------------------------
__global__ void k_final(float* __restrict__ out) {
    int tid = threadIdx.x;
    if (tid < 100) out[tid] = g_flag ? 1.0f : 0.0f;
}

// ---------------------------------------------------------------------------
// Kernel 7: exact conv2 fallback — runs only when nothing was proven
// ---------------------------------------------------------------------------
__global__ void k_conv2_fallback(const unsigned* __restrict__ pool,
                                 const float* __restrict__ w2,
                                 float* __restrict__ out) {
    if (g_flag) return;
    const int y = blockIdx.x;   // 0..126
    const int t = blockIdx.y;   // 0..31
    for (int task = threadIdx.x; task < 127 * 100; task += 128) {
        int x = task / 100;
        int o = task % 100;
        float pot = 0.0f;
        for (int ky = 0; ky < 5; ky++) {
            int ry = y + ky - 1;
            if (ry < 0 || ry > 128) continue;
            for (int kx = 0; kx < 5; kx++) {
                int rx = x + kx - 1;
                if (rx < 0 || rx > 128) continue;
                unsigned m = pool[(t * 129 + ry) * 129 + rx];
                const float* wb = w2 + ((o * 30) * 5 + ky) * 5 + kx;
                for (int i = 0; i < 30; i++) {
                    if ((m >> i) & 1u) pot += wb[i * 25];
                }
            }
        }
        if (pot > 10.0f) out[o] = 1.0f;  // races write the same value; benign
    }
}

// ---------------------------------------------------------------------------
extern "C" void kernel_launch(void* const* d_in, const int* in_sizes, int n_in,
                              void* d_out, int out_size) {
    const float* in = (const float*)d_in[0];   // [32,2,256,256]
    const float* w1 = (const float*)d_in[1];   // [30,2,5,5]
    const float* w2 = (const float*)d_in[2];   // [100,30,5,5]
    float* out = (float*)d_out;                // [1,100]

    unsigned* spk  = nullptr;
    unsigned* pool = nullptr;
    cudaGetSymbolAddress((void**)&spk,  g_spk);
    cudaGetSymbolAddress((void**)&pool, g_pool);

    // fast path: prove all-ones from input popcounts + weight minima
    k_init<<<1, 1>>>();
    k_minw<<<64, 256>>>(w1, in_sizes[1], w2, in_sizes[2]);
    dim3 gp(8, 32);
    k_probe<<<gp, dim3(32, 4)>>>(in);

    // slow path (exact; early-exits when proven)
    dim3 g1(8, 32, 32), b1(32, 4);
    k_conv1<<<g1, b1>>>(in, w1, spk);
    dim3 g2((129 * 129 + 255) / 256, 32);
    k_pool<<<g2, 256>>>(spk, pool);
    dim3 g3((127 * 127 + 255) / 256, 32);
    k_scan<<<g3, 256>>>(pool);

    k_final<<<1, 128>>>(out);
    dim3 g5(127, 32);
    k_conv2_fallback<<<g5, 128>>>(pool, w2, out);
}

// round 4
// speedup vs baseline: 24.4222x; 2.6630x over previous
#include <cuda_runtime.h>

// ---------------- persistent device state (no allocation) -------------------
__device__ unsigned g_spk[32 * 256 * 256];     // conv1 spike bitmask (slow path)
__device__ unsigned g_pool[32 * 129 * 129];    // pooled bitmask (slow path)
__device__ unsigned g_w1min_bits = 0xFFFFFFFFu;
__device__ unsigned g_w2min_bits = 0xFFFFFFFFu;
__device__ unsigned g_Smax_bits  = 0u;         // max window popcount (positive float bits)
__device__ unsigned g_done       = 0u;         // last-block-done counter
__device__ int      g_flag       = 0;          // 1 => provably all-ones (fast path)
__device__ int      g_flag2     = 0;           // slow-path bound-scan result
__device__ volatile unsigned g_gen = 0u;       // grid barrier generation
__device__ unsigned g_cnt = 0u;                // grid barrier counter

// order-preserving float<->uint (min over keys == min over floats, any sign)
__device__ __forceinline__ unsigned f2key(float f) {
    unsigned b = __float_as_uint(f);
    return (b & 0x80000000u) ? ~b : (b | 0x80000000u);
}
__device__ __forceinline__ float key2f(unsigned k) {
    unsigned b = (k & 0x80000000u) ? (k & 0x7FFFFFFFu) : ~k;
    return __uint_as_float(b);
}

// hand-rolled grid barrier: only used on the slow path; all blocks resident
// (grid = 148 <= #SMs, one wave).
__device__ void grid_sync() {
    __syncthreads();
    if (threadIdx.x == 0) {
        unsigned gen = g_gen;
        __threadfence();
        if (atomicAdd(&g_cnt, 1u) == gridDim.x - 1u) {
            g_cnt = 0u;
            __threadfence();
            g_gen = gen + 1u;
        } else {
            while (g_gen == gen) { }
        }
    }
    __syncthreads();
}

// ---------------------------------------------------------------------------
// Kernel 1 (24 blocks x 256): probe + weight minima + flag, fused.
//   blocks 0..15 : popcount-probe a 256x32 slice of t=0 (5x5x2 windows)
//   blocks 16..23: min over w1/w2
//   last-done block: compute g_flag, reset all transient state
// Proof: any window with S active binary inputs has pot1 >= S*w1min (each
// active term >= w1min, valid for any sign). If S*w1min > 15.01 all 30 conv1
// channels spike there; the pooled cell covering it has all 30 bits; every
// pooled cell lies in >=1 conv2 window, and if 30*w2min > 10.01 (=> w2 all
// positive, other terms non-negative) that window's pot2 > 10 for all 100
// output channels => output is exactly all-ones.
// ---------------------------------------------------------------------------
__global__ __launch_bounds__(256) void k_combined(const float* __restrict__ in,
                                                  const float* __restrict__ w1, int n1,
                                                  const float* __restrict__ w2, int n2) {
    const int tid = threadIdx.x;

    if (blockIdx.x < 16) {
        // ---- probe: tile 32 wide x 16 tall, t = 0 ----
        __shared__ float in_s[2][20][36];
        __shared__ float red[256];
        const int x0 = (blockIdx.x & 7) * 32;
        const int y0 = (blockIdx.x >> 3) * 16;
        for (int idx = tid; idx < 1440; idx += 256) {
            int ch = idx / 720, rem = idx % 720;
            int r = rem / 36, c = rem % 36;
            int gy = y0 + r - 2, gx = x0 + c - 2;
            float v = 0.0f;
            if (gy >= 0 && gy < 256 && gx >= 0 && gx < 256)
                v = in[((ch << 8) + gy) * 256 + gx];
            in_s[ch][r][c] = v;
        }
        __syncthreads();
        const int tx = tid & 31, ty2 = (tid >> 5) * 2;
        float s0 = 0.0f, s1 = 0.0f;
        for (int ch = 0; ch < 2; ch++)
#pragma unroll
            for (int i = 0; i < 5; i++)
#pragma unroll
                for (int j = 0; j < 5; j++) {
                    s0 += in_s[ch][ty2 + i][tx + j];
                    s1 += in_s[ch][ty2 + 1 + i][tx + j];
                }
        red[tid] = fmaxf(s0, s1);
        __syncthreads();
        for (int off = 128; off > 0; off >>= 1) {
            if (tid < off) red[tid] = fmaxf(red[tid], red[tid + off]);
            __syncthreads();
        }
        if (tid == 0) atomicMax(&g_Smax_bits, __float_as_uint(red[0]));  // S >= 0
    } else {
        // ---- weight minima: 8 blocks strided over w1 + w2 ----
        const int wb = blockIdx.x - 16;   // 0..7
        float m1 = 1e30f, m2 = 1e30f;
        for (int i = wb * 256 + tid; i < n1; i += 8 * 256) m1 = fminf(m1, w1[i]);
        for (int i = wb * 256 + tid; i < n2; i += 8 * 256) m2 = fminf(m2, w2[i]);
        for (int off = 16; off > 0; off >>= 1) {
            m1 = fminf(m1, __shfl_xor_sync(0xFFFFFFFFu, m1, off));
            m2 = fminf(m2, __shfl_xor_sync(0xFFFFFFFFu, m2, off));
        }
        if ((tid & 31) == 0) {
            atomicMin(&g_w1min_bits, f2key(m1));
            atomicMin(&g_w2min_bits, f2key(m2));
        }
    }

    // ---- last-block-done: compute flag + reset state for next replay ----
    __threadfence();
    __syncthreads();
    if (tid == 0) {
        if (atomicAdd(&g_done, 1u) == gridDim.x - 1u) {
            float Smax  = __uint_as_float(atomicAdd(&g_Smax_bits, 0u));
            float w1min = key2f(atomicAdd(&g_w1min_bits, 0u));
            float w2min = key2f(atomicAdd(&g_w2min_bits, 0u));
            g_flag  = (Smax * w1min > 15.01f && 30.0f * w2min > 10.01f) ? 1 : 0;
            g_flag2 = 0;
            g_Smax_bits  = 0u;
            g_w1min_bits = 0xFFFFFFFFu;
            g_w2min_bits = 0xFFFFFFFFu;
            __threadfence();
            g_done = 0u;
        }
    }
}

// ---------------------------------------------------------------------------
// Kernel 2 (148 blocks x 256): fast path writes all-ones and exits.
// Slow path (never taken on this input, kept for exactness) runs the full
// conv1 -> pool -> bound-scan -> exact conv2 pipeline with grid barriers.
// ---------------------------------------------------------------------------
__global__ __launch_bounds__(256) void k_main(const float* __restrict__ in,
                                              const float* __restrict__ w1,
                                              const float* __restrict__ w2,
                                              unsigned* __restrict__ spk,
                                              unsigned* __restrict__ pool,
                                              float* __restrict__ out) {
    const int tid = threadIdx.x;

    if (*(volatile int*)&g_flag) {                       // uniform across grid
        if (blockIdx.x == 0 && tid < 100) out[tid] = 1.0f;
        return;
    }

    // ======================= slow path (exact) =============================
    __shared__ float in_s[2][12][36];
    __shared__ float w_s[1500];

    // ---- stage 1: conv1 (5x5 pad 2) + fire(>15) -> 30-bit masks ----
    for (int i = tid; i < 1500; i += 256) w_s[i] = w1[i];
    const int tx = tid & 31, ty = tid >> 5;              // 32 x 8
    for (int tile = blockIdx.x; tile < 8192; tile += gridDim.x) {
        const int t  = tile >> 8;
        const int yb = (tile & 255) >> 3;
        const int xb = tile & 7;
        const int x0 = xb * 32, y0 = yb * 8;
        __syncthreads();
        for (int idx = tid; idx < 864; idx += 256) {
            int ch = idx / 432, rem = idx % 432;
            int r = rem / 36, c = rem % 36;
            int gy = y0 + r - 2, gx = x0 + c - 2;
            float v = 0.0f;
            if (gy >= 0 && gy < 256 && gx >= 0 && gx < 256)
                v = in[(((t * 2 + ch) << 8) + gy) * 256 + gx];
            in_s[ch][r][c] = v;
        }
        __syncthreads();
        float acc[30];
#pragma unroll
        for (int o = 0; o < 30; o++) acc[o] = 0.0f;
        int k = 0;
        for (int ch = 0; ch < 2; ch++)
            for (int i = 0; i < 5; i++)
#pragma unroll
                for (int j = 0; j < 5; j++) {
                    float v = in_s[ch][ty + i][tx + j];
#pragma unroll
                    for (int o = 0; o < 30; o++) acc[o] += v * w_s[o * 50 + k];
                    k++;
                }
        unsigned m = 0;
#pragma unroll
        for (int o = 0; o < 30; o++)
            if (acc[o] > 15.0f) m |= (1u << o);
        spk[(t << 16) + ((y0 + ty) << 8) + x0 + tx] = m;
    }
    grid_sync();

    // ---- stage 2: maxpool k=2 s=2 p=1 (OR of 2x2) -> [32,129,129] ----
    for (int idx = blockIdx.x * 256 + tid; idx < 32 * 129 * 129; idx += gridDim.x * 256) {
        int t  = idx / (129 * 129);
        int r  = idx % (129 * 129);
        int py = r / 129, px = r % 129;
        int r0 = 2 * py - 1, r1 = 2 * py;
        int c0 = 2 * px - 1, c1 = 2 * px;
        const unsigned* base = spk + (t << 16);
        unsigned m = 0;
        bool r0v = (r0 >= 0), r1v = (r1 < 256), c0v = (c0 >= 0), c1v = (c1 < 256);
        if (r0v && c0v) m |= base[(r0 << 8) + c0];
        if (r0v && c1v) m |= base[(r0 << 8) + c1];
        if (r1v && c0v) m |= base[(r1 << 8) + c0];
        if (r1v && c1v) m |= base[(r1 << 8) + c1];
        pool[idx] = m;
    }
    grid_sync();

    // ---- stage 3: bound scan (P * w2min > 11 => all channels spike) ----
    {
        float w2min = 1e30f;
        for (int i = tid; i < 75000; i += 256) w2min = fminf(w2min, w2[i]);
        for (int off = 16; off > 0; off >>= 1)
            w2min = fminf(w2min, __shfl_xor_sync(0xFFFFFFFFu, w2min, off));
        __shared__ float wred[8];
        if ((tid & 31) == 0) wred[tid >> 5] = w2min;
        __syncthreads();
        w2min = fminf(fminf(fminf(wred[0], wred[1]), fminf(wred[2], wred[3])),
                      fminf(fminf(wred[4], wred[5]), fminf(wred[6], wred[7])));
        for (int idx = blockIdx.x * 256 + tid; idx < 32 * 127 * 127; idx += gridDim.x * 256) {
            int t = idx / (127 * 127);
            int r = idx % (127 * 127);
            int y = r / 127, x = r % 127;
            int P = 0;
#pragma unroll
            for (int ky = 0; ky < 5; ky++) {
                int ry = y + ky - 1;
                if (ry < 0 || ry > 128) continue;
#pragma unroll
                for (int kx = 0; kx < 5; kx++) {
                    int rx = x + kx - 1;
                    if (rx < 0 || rx > 128) continue;
                    P += __popc(pool[(t * 129 + ry) * 129 + rx]);
                }
            }
            if ((float)P * w2min > 11.0f) g_flag2 = 1;
        }
    }
    grid_sync();

    if (*(volatile int*)&g_flag2) {                      // uniform
        if (blockIdx.x == 0 && tid < 100) out[tid] = 1.0f;
        return;
    }

    // ---- stage 4: exact conv2 fallback ----
    if (blockIdx.x == 0 && tid < 100) out[tid] = 0.0f;
    __threadfence();
    grid_sync();
    for (int pair = blockIdx.x; pair < 127 * 32; pair += gridDim.x) {
        int y = pair % 127, t = pair / 127;
        for (int task = tid; task < 127 * 100; task += 256) {
            int x = task / 100, o = task % 100;
            float pot = 0.0f;
            for (int ky = 0; ky < 5; ky++) {
                int ry = y + ky - 1;
                if (ry < 0 || ry > 128) continue;
                for (int kx = 0; kx < 5; kx++) {
                    int rx = x + kx - 1;
                    if (rx < 0 || rx > 128) continue;
                    unsigned m = pool[(t * 129 + ry) * 129 + rx];
                    const float* wb = w2 + ((o * 30) * 5 + ky) * 5 + kx;
                    for (int i = 0; i < 30; i++)
                        if ((m >> i) & 1u) pot += wb[i * 25];
                }
            }
            if (pot > 10.0f) out[o] = 1.0f;              // benign race, same value
        }
    }
}

// ---------------------------------------------------------------------------
extern "C" void kernel_launch(void* const* d_in, const int* in_sizes, int n_in,
                              void* d_out, int out_size) {
    const float* in = (const float*)d_in[0];   // [32,2,256,256]
    const float* w1 = (const float*)d_in[1];   // [30,2,5,5]
    const float* w2 = (const float*)d_in[2];   // [100,30,5,5]
    float* out = (float*)d_out;                // [1,100]

    unsigned* spk  = nullptr;
    unsigned* pool = nullptr;
    cudaGetSymbolAddress((void**)&spk,  g_spk);
    cudaGetSymbolAddress((void**)&pool, g_pool);

    k_combined<<<24, 256>>>(in, w1, in_sizes[1], w2, in_sizes[2]);
    k_main<<<148, 256>>>(in, w1, w2, spk, pool, out);
}